// round 16
// baseline (speedup 1.0000x reference)
#include <cuda_runtime.h>
#include <cuda_bf16.h>
#include <cstdint>

typedef unsigned long long u64;
typedef unsigned u32;

#define TT 512
#define BB 64
#define DD 512
#define HH 512
#define G4 2048
#define NCTA 128

// ---------------- global scratch ----------------
__device__ float g_G[(size_t)2 * TT * G4 * BB];   // x@Wih^T + bias
__device__ u32 g_Afrag[NCTA][16384];              // Whh frags (phase2)
__device__ u32 g_hfrag[2][2][32768];              // h frags (phase2)
__device__ u32 g_Xfrag[TT][32768];                // x frags (phase1 B)
__device__ u32 g_P1A[2097152];                    // Wih frags (phase1 A) 8MB
__device__ unsigned g_rdy[2][8];                  // per (dir, chunk) publish counters

// ---------------- helpers ----------------
__device__ __forceinline__ float sigf(float x)  { return 1.0f / (1.0f + __expf(-x)); }
__device__ __forceinline__ float tanhfast(float x) {
    return 2.0f / (1.0f + __expf(-2.0f * x)) - 1.0f;
}
__device__ __forceinline__ unsigned smem_u32(const void* p) {
    return (unsigned)__cvta_generic_to_shared(p);
}
__device__ __forceinline__ void cp16(unsigned dst, const void* src) {
    asm volatile("cp.async.cg.shared.global [%0], [%1], 16;" :: "r"(dst), "l"(src) : "memory");
}
__device__ __forceinline__ void cp_commit() { asm volatile("cp.async.commit_group;" ::: "memory"); }
__device__ __forceinline__ void cp_wait0()  { asm volatile("cp.async.wait_group 0;" ::: "memory"); }
__device__ __forceinline__ void cp_wait1()  { asm volatile("cp.async.wait_group 1;" ::: "memory"); }

__device__ __forceinline__ void mbar_init(unsigned a, unsigned c) {
    asm volatile("mbarrier.init.shared.b64 [%0], %1;" :: "r"(a), "r"(c) : "memory");
}
__device__ __forceinline__ void mbar_expect_tx(unsigned a, unsigned b) {
    asm volatile("mbarrier.arrive.expect_tx.shared.b64 _, [%0], %1;" :: "r"(a), "r"(b) : "memory");
}
__device__ __forceinline__ void bulk_g2s(unsigned dst, const void* src, unsigned bytes, unsigned mb) {
    asm volatile("cp.async.bulk.shared::cta.global.mbarrier::complete_tx::bytes [%0], [%1], %2, [%3];"
                 :: "r"(dst), "l"(src), "r"(bytes), "r"(mb) : "memory");
}
__device__ __forceinline__ void mbar_wait(unsigned a, unsigned par) {
    asm volatile(
        "{\n\t.reg .pred P;\n\t"
        "WL_%=:\n\t"
        "mbarrier.try_wait.parity.acquire.cta.shared::cta.b64 P, [%0], %1, 0x989680;\n\t"
        "@P bra.uni WD_%=;\n\t"
        "bra.uni WL_%=;\n\t"
        "WD_%=:\n\t}"
        :: "r"(a), "r"(par) : "memory");
}

__device__ __forceinline__ void mma16816(float* c, const u32* a, u32 b0, u32 b1) {
    asm volatile(
        "mma.sync.aligned.m16n8k16.row.col.f32.bf16.bf16.f32 "
        "{%0,%1,%2,%3}, {%4,%5,%6,%7}, {%8,%9}, {%0,%1,%2,%3};"
        : "+f"(c[0]), "+f"(c[1]), "+f"(c[2]), "+f"(c[3])
        : "r"(a[0]), "r"(a[1]), "r"(a[2]), "r"(a[3]), "r"(b0), "r"(b1));
}
__device__ __forceinline__ u32 packbf2(float e0, float e1) {
    __nv_bfloat162 v = __float22bfloat162_rn(make_float2(e0, e1));
    return *(u32*)&v;
}

// ---------------- xconv: x -> B-fragment images (same layout as h frags) ----
__global__ void __launch_bounds__(256) xconv_kernel(const float* __restrict__ x)
{
    int idx = blockIdx.x * 256 + threadIdx.x;    // 8,388,608
    int reg = idx & 1;
    int lane = (idx >> 1) & 31;
    int n8t = (idx >> 6) & 7;
    int ks  = (idx >> 9) & 31;
    int t   = idx >> 14;
    int g = lane >> 2, t4 = lane & 3;
    int b = n8t * 8 + g;
    int k = ks * 16 + reg * 8 + t4 * 2;
    const float* xp = x + ((size_t)t * BB + b) * DD + k;
    float x0 = xp[0], x1 = xp[1];
    float h0 = __bfloat162float(__float2bfloat16(x0));
    float h1 = __bfloat162float(__float2bfloat16(x1));
    u32* dst = g_Xfrag[t];
    dst[((ks * 2 + 0) * 8 + n8t) * 64 + lane * 2 + reg] = packbf2(x0, x1);
    dst[((ks * 2 + 1) * 8 + n8t) * 64 + lane * 2 + reg] = packbf2(x0 - h0, x1 - h1);
}

// ---------------- prep1: Wih A-fragment images (256 blocks) -----------------
__global__ void __launch_bounds__(256) prep1_kernel(
    const float* __restrict__ Wf, const float* __restrict__ Wr)
{
    const int bg  = blockIdx.x >> 3;      // dir*16+mg
    const int sub = blockIdx.x & 7;
    const int dir = bg >> 4, mg = bg & 15;
    const float* __restrict__ W = dir ? Wr : Wf;
    u32* dst = g_P1A + (size_t)bg * 65536;
    for (int q = threadIdx.x; q < 8192; q += 256) {
        int idx = sub * 8192 + q;
        int reg = idx & 3;
        int lane = (idx >> 2) & 31;
        int ksl = (idx >> 7) & 3;
        int mt8 = (idx >> 9) & 7;
        int hl  = (idx >> 12) & 1;
        int kc  = idx >> 13;
        int g = lane >> 2, t4 = lane & 3;
        int m = mg * 128 + mt8 * 16 + g + ((reg & 1) ? 8 : 0);
        int k = kc * 64 + ksl * 16 + 2 * t4 + ((reg & 2) ? 8 : 0);
        const float* wp = W + (size_t)m * DD + k;
        float w0 = wp[0], w1 = wp[1];
        if (hl == 0) dst[idx] = packbf2(w0, w1);
        else {
            float r0 = w0 - __bfloat162float(__float2bfloat16(w0));
            float r1 = w1 - __bfloat162float(__float2bfloat16(w1));
            dst[idx] = packbf2(r0, r1);
        }
    }
}

// ---------------- phase1_mma: G = x@Wih^T + bias via mma.sync ---------------
#define P1_STAGE 65536
#define P1_BIAS  131072
#define P1_SMEM  131584

#define P1_ISSUE(c, slot) do {                                                  \
    unsigned sa = smem_u32(smem + (slot) * P1_STAGE);                           \
    const char* as = (const char*)(Abase + (size_t)(c) * 8192);                 \
    _Pragma("unroll")                                                           \
    for (int i = 0; i < 8; i++)                                                 \
        cp16(sa + (unsigned)(tid + 256 * i) * 16u, as + (size_t)(tid + 256 * i) * 16); \
    unsigned sb = sa + 32768u;                                                  \
    const char* b0 = (const char*)(B0 + (size_t)(c) * 4096);                    \
    const char* b1 = (const char*)(B1 + (size_t)(c) * 4096);                    \
    _Pragma("unroll")                                                           \
    for (int i = 0; i < 4; i++) {                                               \
        cp16(sb + (unsigned)(tid + 256 * i) * 16u, b0 + (size_t)(tid + 256 * i) * 16); \
        cp16(sb + 16384u + (unsigned)(tid + 256 * i) * 16u, b1 + (size_t)(tid + 256 * i) * 16); \
    }                                                                           \
    cp_commit();                                                                \
} while (0)

__global__ void __launch_bounds__(256) phase1_mma_kernel(
    const float* __restrict__ bif, const float* __restrict__ bhf,
    const float* __restrict__ bir, const float* __restrict__ bhr)
{
    extern __shared__ __align__(16) char smem[];
    const int tid = threadIdx.x;
    const int mg = blockIdx.x, tp = blockIdx.y, dir = blockIdx.z;
    float* bias = (float*)(smem + P1_BIAS);
    if (tid < 128) {
        int n = mg * 128 + tid;
        bias[tid] = dir ? (bir[n] + bhr[n]) : (bif[n] + bhf[n]);
    }
    const u32* Abase = g_P1A + (size_t)(dir * 16 + mg) * 65536;
    const u32* B0 = g_Xfrag[tp * 2];
    const u32* B1 = g_Xfrag[tp * 2 + 1];

    P1_ISSUE(0, 0);
    P1_ISSUE(1, 1);

    const int w = tid >> 5, lane = tid & 31;
    const int lg = lane >> 2, lt = lane & 3;
    float cf[16][4];
#pragma unroll
    for (int j = 0; j < 16; j++)
#pragma unroll
        for (int r = 0; r < 4; r++) cf[j][r] = 0.0f;

    for (int ch = 0; ch < 8; ch++) {
        if (ch == 7) cp_wait0(); else cp_wait1();
        __syncthreads();
        const char* As = smem + (ch & 1) * P1_STAGE;
        const char* Bs = As + 32768;
#pragma unroll
        for (int ksl = 0; ksl < 4; ksl++) {
            uint4 vh = *(const uint4*)(As + ((size_t)(w * 4 + ksl) * 128 + lane * 4) * 4);
            uint4 vl = *(const uint4*)(As + 16384 + ((size_t)(w * 4 + ksl) * 128 + lane * 4) * 4);
            u32 ah[4] = {vh.x, vh.y, vh.z, vh.w};
            u32 al[4] = {vl.x, vl.y, vl.z, vl.w};
#pragma unroll
            for (int j = 0; j < 16; j++) {
                const int t_loc = j >> 3, n8t = j & 7;
                const char* bb = Bs + t_loc * 16384
                    + ((size_t)((ksl * 2 + 0) * 8 + n8t) * 32 + lane) * 8;
                u64 bh = *(const u64*)bb;
                u64 bl = *(const u64*)(bb + 2048);
                mma16816(cf[j], ah, (u32)bh, (u32)(bh >> 32));
                mma16816(cf[j], al, (u32)bh, (u32)(bh >> 32));
                mma16816(cf[j], ah, (u32)bl, (u32)(bl >> 32));
            }
        }
        __syncthreads();
        if (ch + 2 < 8) P1_ISSUE(ch + 2, ch & 1);
    }

    const int r0 = mg * 128 + w * 16 + lg;
    const float bs0 = bias[w * 16 + lg];
    const float bs1 = bias[w * 16 + lg + 8];
#pragma unroll
    for (int j = 0; j < 16; j++) {
        int n = j * 8 + 2 * lt;
        int t_loc = n >> 6, b = n & 63;
        int t = tp * 2 + t_loc;
        int s = dir ? (TT - 1 - t) : t;
        float* gp = g_G + ((size_t)(dir * TT + s) * G4 + r0) * BB + b;
        *(float2*)gp = make_float2(cf[j][0] + bs0, cf[j][1] + bs0);
        *(float2*)(gp + 8 * BB) = make_float2(cf[j][2] + bs1, cf[j][3] + bs1);
    }
}

// ---------------- prep: Whh fragment images + resets ------------------------
__global__ void __launch_bounds__(256) prep_kernel(
    const float* __restrict__ Whf, const float* __restrict__ Whr)
{
    const int cid = blockIdx.x;
    const int dir = cid >> 6;
    const int j0  = (cid & 63) * 8;
    const float* __restrict__ W = dir ? Whr : Whf;
    for (int idx = threadIdx.x; idx < 16384; idx += 256) {
        int hl = idx >> 13;
        int rem = idx & 8191;
        int mt = rem >> 12;
        int ks = (rem >> 7) & 31;
        int lane = (rem >> 2) & 31;
        int reg = rem & 3;
        int g = lane >> 2, t = lane & 3;
        int m = mt * 16 + g + ((reg & 1) ? 8 : 0);
        int k = ks * 16 + 2 * t + ((reg & 2) ? 8 : 0);
        int gate = m >> 3, u = m & 7;
        const float* wr = W + (size_t)(gate * HH + j0 + u) * HH + k;
        float w0 = wr[0], w1 = wr[1];
        if (hl == 0) {
            g_Afrag[cid][idx] = packbf2(w0, w1);
        } else {
            float r0 = w0 - __bfloat162float(__float2bfloat16(w0));
            float r1 = w1 - __bfloat162float(__float2bfloat16(w1));
            g_Afrag[cid][idx] = packbf2(r0, r1);
        }
    }
    {
        int i = blockIdx.x * 256 + threadIdx.x;
        u64* Z = (u64*)&g_hfrag[0][0][0];
        if (i < 32768) Z[i] = 0ull;
    }
    if (cid == 0 && threadIdx.x < 16)
        ((unsigned*)g_rdy)[threadIdx.x] = 0;
}

// ---------------- Phase 2: 16-warp dataflow-synced mma recurrence -----------
#define SB_AF  0
#define SB_HF  65536
#define SB_DEX 205312
#define SB_CS  222208
#define SB_HS  224320
#define SB_MB  226688
#define SMEM2  226816

__global__ void __launch_bounds__(512) phase2_kernel(
    const float* __restrict__ mask, float* __restrict__ out)
{
    extern __shared__ __align__(16) char smem[];
    float* Dex = (float*)(smem + SB_DEX);
    float* cs  = (float*)(smem + SB_CS);
    float* hs  = (float*)(smem + SB_HS);
    const unsigned af_sa = smem_u32(smem + SB_AF);
    const unsigned hf_sa = smem_u32(smem + SB_HF);
    const unsigned MB    = smem_u32(smem + SB_MB);

    const int tid = threadIdx.x;
    const int cid = blockIdx.x;
    const int dir = cid >> 6;
    const int j0  = (cid & 63) * 8;
    const int mychunk = (cid & 63) >> 3;

    if (tid < 8) mbar_init(MB + tid * 8, 1);
    for (int i = tid; i < 528; i += 512) { cs[i] = 0.0f; hs[i] = 0.0f; }
#pragma unroll
    for (int r = 0; r < 8; r++) {
        unsigned o = (unsigned)(tid + 512 * r) * 16u;
        cp16(af_sa + o, (const char*)&g_Afrag[cid][0] + o);
    }
    cp_commit();
    cp_wait0();
    __syncthreads();

    const int wid  = tid >> 5;
    const int lane = tid & 31;
    const int mt   = wid & 1;
    const int kh   = (wid >> 1) & 3;          // k quarter
    const int nh   = wid >> 3;
    const int lg   = lane >> 2, lt = lane & 3;
    const int b    = tid & 63;
    const int u0   = ((tid & 255) >> 6) * 2;

    // prologue: issue step-0 bulks, one chunk per warp (warps 0..7)
    if (lane == 0 && wid < 8) {
        mbar_expect_tx(MB + wid * 8, 16384u);
        bulk_g2s(hf_sa + (unsigned)wid * 16384u,
                 &g_hfrag[0][dir][wid * 4096], 16384u, MB + wid * 8);
    }

    for (int s = 0; s < TT; s++) {
        const int nb = (s & 1) ^ 1;
        const int tg = dir ? (TT - 1 - s) : s;

        // G + mask prefetch into registers (tid<256 epilogue threads only)
        float gv[2][4];
        float m = 0.0f;
        if (tid < 256) {
            const float* gbase = g_G + ((size_t)(dir * TT + s) * G4) * BB + b;
#pragma unroll
            for (int q = 0; q < 2; q++) {
                const int u = u0 + q;
#pragma unroll
                for (int g = 0; g < 4; g++)
                    gv[q][g] = __ldg(gbase + (size_t)(g * HH + j0 + u) * BB);
            }
            m = __ldg(mask + (size_t)tg * BB + b);
        }

        // ---- GEMM: all warps ride the chunk-arrival wave (chunk = ki) ----
        float c[4][4];
#pragma unroll
        for (int j = 0; j < 4; j++)
#pragma unroll
            for (int r = 0; r < 4; r++) c[j][r] = 0.0f;

#pragma unroll 4
        for (int ki = 0; ki < 8; ki++) {
            const int ks = ki * 4 + kh;
            mbar_wait(MB + ki * 8, (unsigned)(s & 1));
            u32 ah[4], al[4];
            {
                uint4 v = *(const uint4*)(smem + SB_AF +
                    ((size_t)((mt * 32 + ks) * 32 + lane)) * 16);
                ah[0] = v.x; ah[1] = v.y; ah[2] = v.z; ah[3] = v.w;
                uint4 w2 = *(const uint4*)(smem + SB_AF + 65536 / 2 +
                    ((size_t)((mt * 32 + ks) * 32 + lane)) * 16);
                al[0] = w2.x; al[1] = w2.y; al[2] = w2.z; al[3] = w2.w;
            }
#pragma unroll
            for (int j = 0; j < 4; j++) {
                const int n8t = nh * 4 + j;
                const char* bb = smem + SB_HF +
                    ((size_t)((ks * 2 + 0) * 8 + n8t) * 32 + lane) * 8;
                u64 bh = *(const u64*)bb;
                u64 bl = *(const u64*)(bb + 512 * 4);
                u32 bh0 = (u32)bh, bh1 = (u32)(bh >> 32);
                u32 bl0 = (u32)bl, bl1 = (u32)(bl >> 32);
                mma16816(c[j], ah, bh0, bh1);
                mma16816(c[j], al, bh0, bh1);
                mma16816(c[j], ah, bl0, bl1);
            }
        }

        // 2-pass reduction into 2 planes (kh 0/1 write, kh 2/3 add)
        {
            float* dp = Dex + (kh & 1) * 2112;
            const int row0 = mt * 16 + lg;
            if (kh < 2) {
#pragma unroll
                for (int j = 0; j < 4; j++) {
                    const int col = (nh * 4 + j) * 8 + 2 * lt;
                    *(float2*)&dp[row0 * 66 + col]       = make_float2(c[j][0], c[j][1]);
                    *(float2*)&dp[(row0 + 8) * 66 + col] = make_float2(c[j][2], c[j][3]);
                }
            }
            __syncthreads();
            if (kh >= 2) {
#pragma unroll
                for (int j = 0; j < 4; j++) {
                    const int col = (nh * 4 + j) * 8 + 2 * lt;
                    float2 p0 = *(float2*)&dp[row0 * 66 + col];
                    float2 p1 = *(float2*)&dp[(row0 + 8) * 66 + col];
                    *(float2*)&dp[row0 * 66 + col] =
                        make_float2(p0.x + c[j][0], p0.y + c[j][1]);
                    *(float2*)&dp[(row0 + 8) * 66 + col] =
                        make_float2(p1.x + c[j][2], p1.y + c[j][3]);
                }
            }
        }
        __syncthreads();

        // ---- epilogue (tid<256): publish h first, then signal, then out ----
        float hn[2];
        if (tid < 256) {
#pragma unroll
            for (int q = 0; q < 2; q++) {
                const int u = u0 + q;
                float pi = Dex[u * 66 + b]        + Dex[2112 + u * 66 + b]        + gv[q][0];
                float pf = Dex[(8 + u) * 66 + b]  + Dex[2112 + (8 + u) * 66 + b]  + gv[q][1];
                float pg = Dex[(16 + u) * 66 + b] + Dex[2112 + (16 + u) * 66 + b] + gv[q][2];
                float po = Dex[(24 + u) * 66 + b] + Dex[2112 + (24 + u) * 66 + b] + gv[q][3];
                float ig = sigf(pi), fg = sigf(pf);
                float gg = tanhfast(pg), og = sigf(po);
                float c_old = cs[u * 66 + b];
                float c2 = fg * c_old + ig * gg;
                float h2 = og * tanhfast(c2);
                float c_new = c_old + m * (c2 - c_old);
                float h_old = hs[u * 66 + b];
                float h_new = h_old + m * (h2 - h_old);
                cs[u * 66 + b] = c_new;
                hs[u * 66 + b] = h_new;
                hn[q] = h_new;
            }
            float b0h = __bfloat162float(__float2bfloat16(hn[0]));
            float b1h = __bfloat162float(__float2bfloat16(hn[1]));
            u32 hi = packbf2(hn[0], hn[1]);
            u32 lo = packbf2(hn[0] - b0h, hn[1] - b1h);
            const int ks2 = j0 >> 4;
            const int reg = (j0 & 15) >> 3;
            const int n8t = b >> 3;
            const int lane2 = (b & 7) * 4 + (u0 >> 1);
            u32* dst = &g_hfrag[nb][dir][((ks2 * 2 + 0) * 8 + n8t) * 64 + lane2 * 2 + reg];
            dst[0]   = hi;
            dst[512] = lo;
        }
        __threadfence();
        __syncthreads();
        if (tid == 0) atomicAdd(&g_rdy[dir][mychunk], 1u);

        // loader for step s+1: one chunk per warp (warps 0..7), parallel spins
        if (s + 1 < TT && lane == 0 && wid < 8) {
            const unsigned target = 8u * (unsigned)(s + 1);
            while (*(volatile unsigned*)&g_rdy[dir][wid] < target) { }
            mbar_expect_tx(MB + wid * 8, 16384u);
            bulk_g2s(hf_sa + (unsigned)wid * 16384u,
                     &g_hfrag[nb][dir][wid * 4096], 16384u, MB + wid * 8);
        }

        // output store
        if (tid < 256)
            *(float2*)&out[(size_t)tg * (BB * 1024) + (size_t)b * 1024
                           + dir * HH + j0 + u0] = make_float2(hn[0], hn[1]);
    }
}

// ---------------- Launch ----------------
extern "C" void kernel_launch(void* const* d_in, const int* in_sizes, int n_in,
                              void* d_out, int out_size) {
    const float* x_data = (const float*)d_in[0];
    const float* x_mask = (const float*)d_in[1];
    const float* Wih_f  = (const float*)d_in[2];
    const float* Whh_f  = (const float*)d_in[3];
    const float* bih_f  = (const float*)d_in[4];
    const float* bhh_f  = (const float*)d_in[5];
    const float* Wih_r  = (const float*)d_in[6];
    const float* Whh_r  = (const float*)d_in[7];
    const float* bih_r  = (const float*)d_in[8];
    const float* bhh_r  = (const float*)d_in[9];
    float* out = (float*)d_out;

    static bool attr_set = false;
    if (!attr_set) {
        cudaFuncSetAttribute(phase2_kernel,
                             cudaFuncAttributeMaxDynamicSharedMemorySize, SMEM2);
        cudaFuncSetAttribute(phase1_mma_kernel,
                             cudaFuncAttributeMaxDynamicSharedMemorySize, P1_SMEM);
        attr_set = true;
    }
    xconv_kernel<<<32768, 256>>>(x_data);
    prep1_kernel<<<256, 256>>>(Wih_f, Wih_r);
    prep_kernel<<<NCTA, 256>>>(Whh_f, Whh_r);
    phase1_mma_kernel<<<dim3(16, 256, 2), 256, P1_SMEM>>>(bih_f, bhh_f, bih_r, bhh_r);
    phase2_kernel<<<NCTA, 512, SMEM2>>>(x_mask, out);
}

// round 17
// speedup vs baseline: 1.0695x; 1.0695x over previous
#include <cuda_runtime.h>
#include <cuda_bf16.h>
#include <cstdint>

typedef unsigned long long u64;
typedef unsigned u32;

#define TT 512
#define BB 64
#define DD 512
#define HH 512
#define G4 2048
#define NCTA 128

// ---------------- global scratch ----------------
__device__ float g_G[(size_t)2 * TT * G4 * BB];   // x@Wih^T + bias
__device__ u32 g_Afrag[NCTA][16384];              // Whh frags (phase2)
__device__ u32 g_hfrag[2][2][32768];              // h frags (phase2)
__device__ u32 g_Xfrag[TT][32768];                // x frags (phase1 B)
__device__ u32 g_P1A[2097152];                    // Wih frags (phase1 A) 8MB
__device__ unsigned g_rdy[2][8];                  // per (dir, chunk) publish counters

// ---------------- helpers ----------------
__device__ __forceinline__ float sigf(float x)  { return 1.0f / (1.0f + __expf(-x)); }
__device__ __forceinline__ float tanhfast(float x) {
    return 2.0f / (1.0f + __expf(-2.0f * x)) - 1.0f;
}
__device__ __forceinline__ unsigned smem_u32(const void* p) {
    return (unsigned)__cvta_generic_to_shared(p);
}
__device__ __forceinline__ void cp16(unsigned dst, const void* src) {
    asm volatile("cp.async.cg.shared.global [%0], [%1], 16;" :: "r"(dst), "l"(src) : "memory");
}
__device__ __forceinline__ void cp_commit() { asm volatile("cp.async.commit_group;" ::: "memory"); }
__device__ __forceinline__ void cp_wait0()  { asm volatile("cp.async.wait_group 0;" ::: "memory"); }
__device__ __forceinline__ void cp_wait1()  { asm volatile("cp.async.wait_group 1;" ::: "memory"); }

__device__ __forceinline__ void mbar_init(unsigned a, unsigned c) {
    asm volatile("mbarrier.init.shared.b64 [%0], %1;" :: "r"(a), "r"(c) : "memory");
}
__device__ __forceinline__ void mbar_expect_tx(unsigned a, unsigned b) {
    asm volatile("mbarrier.arrive.expect_tx.shared.b64 _, [%0], %1;" :: "r"(a), "r"(b) : "memory");
}
__device__ __forceinline__ void bulk_g2s(unsigned dst, const void* src, unsigned bytes, unsigned mb) {
    asm volatile("cp.async.bulk.shared::cta.global.mbarrier::complete_tx::bytes [%0], [%1], %2, [%3];"
                 :: "r"(dst), "l"(src), "r"(bytes), "r"(mb) : "memory");
}
__device__ __forceinline__ void mbar_wait(unsigned a, unsigned par) {
    asm volatile(
        "{\n\t.reg .pred P;\n\t"
        "WL_%=:\n\t"
        "mbarrier.try_wait.parity.acquire.cta.shared::cta.b64 P, [%0], %1, 0x989680;\n\t"
        "@P bra.uni WD_%=;\n\t"
        "bra.uni WL_%=;\n\t"
        "WD_%=:\n\t}"
        :: "r"(a), "r"(par) : "memory");
}

__device__ __forceinline__ void mma16816(float* c, const u32* a, u32 b0, u32 b1) {
    asm volatile(
        "mma.sync.aligned.m16n8k16.row.col.f32.bf16.bf16.f32 "
        "{%0,%1,%2,%3}, {%4,%5,%6,%7}, {%8,%9}, {%0,%1,%2,%3};"
        : "+f"(c[0]), "+f"(c[1]), "+f"(c[2]), "+f"(c[3])
        : "r"(a[0]), "r"(a[1]), "r"(a[2]), "r"(a[3]), "r"(b0), "r"(b1));
}
__device__ __forceinline__ u32 packbf2(float e0, float e1) {
    __nv_bfloat162 v = __float22bfloat162_rn(make_float2(e0, e1));
    return *(u32*)&v;
}

// ---------------- xconv: x -> B-fragment images (same layout as h frags) ----
__global__ void __launch_bounds__(256) xconv_kernel(const float* __restrict__ x)
{
    int idx = blockIdx.x * 256 + threadIdx.x;    // 8,388,608
    int reg = idx & 1;
    int lane = (idx >> 1) & 31;
    int n8t = (idx >> 6) & 7;
    int ks  = (idx >> 9) & 31;
    int t   = idx >> 14;
    int g = lane >> 2, t4 = lane & 3;
    int b = n8t * 8 + g;
    int k = ks * 16 + reg * 8 + t4 * 2;
    const float* xp = x + ((size_t)t * BB + b) * DD + k;
    float x0 = xp[0], x1 = xp[1];
    float h0 = __bfloat162float(__float2bfloat16(x0));
    float h1 = __bfloat162float(__float2bfloat16(x1));
    u32* dst = g_Xfrag[t];
    dst[((ks * 2 + 0) * 8 + n8t) * 64 + lane * 2 + reg] = packbf2(x0, x1);
    dst[((ks * 2 + 1) * 8 + n8t) * 64 + lane * 2 + reg] = packbf2(x0 - h0, x1 - h1);
}

// ---------------- prep1: Wih A-fragment images (256 blocks) -----------------
__global__ void __launch_bounds__(256) prep1_kernel(
    const float* __restrict__ Wf, const float* __restrict__ Wr)
{
    const int bg  = blockIdx.x >> 3;      // dir*16+mg
    const int sub = blockIdx.x & 7;
    const int dir = bg >> 4, mg = bg & 15;
    const float* __restrict__ W = dir ? Wr : Wf;
    u32* dst = g_P1A + (size_t)bg * 65536;
    for (int q = threadIdx.x; q < 8192; q += 256) {
        int idx = sub * 8192 + q;
        int reg = idx & 3;
        int lane = (idx >> 2) & 31;
        int ksl = (idx >> 7) & 3;
        int mt8 = (idx >> 9) & 7;
        int hl  = (idx >> 12) & 1;
        int kc  = idx >> 13;
        int g = lane >> 2, t4 = lane & 3;
        int m = mg * 128 + mt8 * 16 + g + ((reg & 1) ? 8 : 0);
        int k = kc * 64 + ksl * 16 + 2 * t4 + ((reg & 2) ? 8 : 0);
        const float* wp = W + (size_t)m * DD + k;
        float w0 = wp[0], w1 = wp[1];
        if (hl == 0) dst[idx] = packbf2(w0, w1);
        else {
            float r0 = w0 - __bfloat162float(__float2bfloat16(w0));
            float r1 = w1 - __bfloat162float(__float2bfloat16(w1));
            dst[idx] = packbf2(r0, r1);
        }
    }
}

// ---------------- phase1_mma: G = x@Wih^T + bias via mma.sync ---------------
#define P1_STAGE 65536
#define P1_BIAS  131072
#define P1_SMEM  131584

#define P1_ISSUE(c, slot) do {                                                  \
    unsigned sa = smem_u32(smem + (slot) * P1_STAGE);                           \
    const char* as = (const char*)(Abase + (size_t)(c) * 8192);                 \
    _Pragma("unroll")                                                           \
    for (int i = 0; i < 8; i++)                                                 \
        cp16(sa + (unsigned)(tid + 256 * i) * 16u, as + (size_t)(tid + 256 * i) * 16); \
    unsigned sb = sa + 32768u;                                                  \
    const char* b0 = (const char*)(B0 + (size_t)(c) * 4096);                    \
    const char* b1 = (const char*)(B1 + (size_t)(c) * 4096);                    \
    _Pragma("unroll")                                                           \
    for (int i = 0; i < 4; i++) {                                               \
        cp16(sb + (unsigned)(tid + 256 * i) * 16u, b0 + (size_t)(tid + 256 * i) * 16); \
        cp16(sb + 16384u + (unsigned)(tid + 256 * i) * 16u, b1 + (size_t)(tid + 256 * i) * 16); \
    }                                                                           \
    cp_commit();                                                                \
} while (0)

__global__ void __launch_bounds__(256) phase1_mma_kernel(
    const float* __restrict__ bif, const float* __restrict__ bhf,
    const float* __restrict__ bir, const float* __restrict__ bhr)
{
    extern __shared__ __align__(16) char smem[];
    const int tid = threadIdx.x;
    const int mg = blockIdx.x, tp = blockIdx.y, dir = blockIdx.z;
    float* bias = (float*)(smem + P1_BIAS);
    if (tid < 128) {
        int n = mg * 128 + tid;
        bias[tid] = dir ? (bir[n] + bhr[n]) : (bif[n] + bhf[n]);
    }
    const u32* Abase = g_P1A + (size_t)(dir * 16 + mg) * 65536;
    const u32* B0 = g_Xfrag[tp * 2];
    const u32* B1 = g_Xfrag[tp * 2 + 1];

    P1_ISSUE(0, 0);
    P1_ISSUE(1, 1);

    const int w = tid >> 5, lane = tid & 31;
    const int lg = lane >> 2, lt = lane & 3;
    float cf[16][4];
#pragma unroll
    for (int j = 0; j < 16; j++)
#pragma unroll
        for (int r = 0; r < 4; r++) cf[j][r] = 0.0f;

    for (int ch = 0; ch < 8; ch++) {
        if (ch == 7) cp_wait0(); else cp_wait1();
        __syncthreads();
        const char* As = smem + (ch & 1) * P1_STAGE;
        const char* Bs = As + 32768;
#pragma unroll
        for (int ksl = 0; ksl < 4; ksl++) {
            uint4 vh = *(const uint4*)(As + ((size_t)(w * 4 + ksl) * 128 + lane * 4) * 4);
            uint4 vl = *(const uint4*)(As + 16384 + ((size_t)(w * 4 + ksl) * 128 + lane * 4) * 4);
            u32 ah[4] = {vh.x, vh.y, vh.z, vh.w};
            u32 al[4] = {vl.x, vl.y, vl.z, vl.w};
#pragma unroll
            for (int j = 0; j < 16; j++) {
                const int t_loc = j >> 3, n8t = j & 7;
                const char* bb = Bs + t_loc * 16384
                    + ((size_t)((ksl * 2 + 0) * 8 + n8t) * 32 + lane) * 8;
                u64 bh = *(const u64*)bb;
                u64 bl = *(const u64*)(bb + 2048);
                mma16816(cf[j], ah, (u32)bh, (u32)(bh >> 32));
                mma16816(cf[j], al, (u32)bh, (u32)(bh >> 32));
                mma16816(cf[j], ah, (u32)bl, (u32)(bl >> 32));
            }
        }
        __syncthreads();
        if (ch + 2 < 8) P1_ISSUE(ch + 2, ch & 1);
    }

    const int r0 = mg * 128 + w * 16 + lg;
    const float bs0 = bias[w * 16 + lg];
    const float bs1 = bias[w * 16 + lg + 8];
#pragma unroll
    for (int j = 0; j < 16; j++) {
        int n = j * 8 + 2 * lt;
        int t_loc = n >> 6, b = n & 63;
        int t = tp * 2 + t_loc;
        int s = dir ? (TT - 1 - t) : t;
        float* gp = g_G + ((size_t)(dir * TT + s) * G4 + r0) * BB + b;
        *(float2*)gp = make_float2(cf[j][0] + bs0, cf[j][1] + bs0);
        *(float2*)(gp + 8 * BB) = make_float2(cf[j][2] + bs1, cf[j][3] + bs1);
    }
}

// ---------------- prep: Whh fragment images + resets ------------------------
__global__ void __launch_bounds__(256) prep_kernel(
    const float* __restrict__ Whf, const float* __restrict__ Whr)
{
    const int cid = blockIdx.x;
    const int dir = cid >> 6;
    const int j0  = (cid & 63) * 8;
    const float* __restrict__ W = dir ? Whr : Whf;
    for (int idx = threadIdx.x; idx < 16384; idx += 256) {
        int hl = idx >> 13;
        int rem = idx & 8191;
        int mt = rem >> 12;
        int ks = (rem >> 7) & 31;
        int lane = (rem >> 2) & 31;
        int reg = rem & 3;
        int g = lane >> 2, t = lane & 3;
        int m = mt * 16 + g + ((reg & 1) ? 8 : 0);
        int k = ks * 16 + 2 * t + ((reg & 2) ? 8 : 0);
        int gate = m >> 3, u = m & 7;
        const float* wr = W + (size_t)(gate * HH + j0 + u) * HH + k;
        float w0 = wr[0], w1 = wr[1];
        if (hl == 0) {
            g_Afrag[cid][idx] = packbf2(w0, w1);
        } else {
            float r0 = w0 - __bfloat162float(__float2bfloat16(w0));
            float r1 = w1 - __bfloat162float(__float2bfloat16(w1));
            g_Afrag[cid][idx] = packbf2(r0, r1);
        }
    }
    {
        int i = blockIdx.x * 256 + threadIdx.x;
        u64* Z = (u64*)&g_hfrag[0][0][0];
        if (i < 32768) Z[i] = 0ull;
    }
    if (cid == 0 && threadIdx.x < 16)
        ((unsigned*)g_rdy)[threadIdx.x] = 0;
}

// ---------------- Phase 2: dataflow-synced persistent mma recurrence --------
#define SB_AF  0
#define SB_HF  65536
#define SB_DEX 205312
#define SB_CS  222208
#define SB_HS  224320
#define SB_MB  226688
#define SMEM2  226816

__global__ void __launch_bounds__(256) phase2_kernel(
    const float* __restrict__ mask, float* __restrict__ out)
{
    extern __shared__ __align__(16) char smem[];
    float* Dex = (float*)(smem + SB_DEX);
    float* cs  = (float*)(smem + SB_CS);
    float* hs  = (float*)(smem + SB_HS);
    const unsigned af_sa = smem_u32(smem + SB_AF);
    const unsigned hf_sa = smem_u32(smem + SB_HF);
    const unsigned MB    = smem_u32(smem + SB_MB);

    const int tid = threadIdx.x;
    const int cid = blockIdx.x;
    const int dir = cid >> 6;
    const int j0  = (cid & 63) * 8;
    const int mychunk = (cid & 63) >> 3;

    if (tid < 8) mbar_init(MB + tid * 8, 1);
    for (int i = tid; i < 528; i += 256) { cs[i] = 0.0f; hs[i] = 0.0f; }
#pragma unroll
    for (int r = 0; r < 16; r++) {
        unsigned o = (unsigned)(tid + 256 * r) * 16u;
        cp16(af_sa + o, (const char*)&g_Afrag[cid][0] + o);
    }
    cp_commit();
    cp_wait0();
    __syncthreads();

    const int wid  = tid >> 5;
    const int lane = tid & 31;
    const int mt   = wid & 1;
    const int kh   = (wid >> 1) & 1;
    const int nh   = wid >> 2;
    const int lg   = lane >> 2, lt = lane & 3;
    const int b    = tid & 63;
    const int u0   = (tid >> 6) * 2;

    // prologue: issue step-0 bulks, one chunk per warp (parallel)
    if (lane == 0) {
        mbar_expect_tx(MB + wid * 8, 16384u);
        bulk_g2s(hf_sa + (unsigned)wid * 16384u,
                 &g_hfrag[0][dir][wid * 4096], 16384u, MB + wid * 8);
    }

    for (int s = 0; s < TT; s++) {
        const int nb = (s & 1) ^ 1;
        const int tg = dir ? (TT - 1 - s) : s;

        // G + mask prefetch into REGISTERS (consumed in epilogue; fully hidden)
        float gv[2][4];
        {
            const float* gbase = g_G + ((size_t)(dir * TT + s) * G4) * BB + b;
#pragma unroll
            for (int q = 0; q < 2; q++) {
                const int u = u0 + q;
#pragma unroll
                for (int g = 0; g < 4; g++)
                    gv[q][g] = __ldg(gbase + (size_t)(g * HH + j0 + u) * BB);
            }
        }
        const float m = __ldg(mask + (size_t)tg * BB + b);

        // ---- GEMM: interleaved chunk striping (kh half rides early chunks) ----
        float c[4][4];
#pragma unroll
        for (int j = 0; j < 4; j++)
#pragma unroll
            for (int r = 0; r < 4; r++) c[j][r] = 0.0f;

#pragma unroll 4
        for (int ki = 0; ki < 16; ki++) {
            const int ks = (ki >> 2) * 8 + kh * 4 + (ki & 3);
            if ((ki & 3) == 0) mbar_wait(MB + ((ki >> 2) * 2 + kh) * 8, (unsigned)(s & 1));
            u32 ah[4], al[4];
            {
                uint4 v = *(const uint4*)(smem + SB_AF +
                    ((size_t)((mt * 32 + ks) * 32 + lane)) * 16);
                ah[0] = v.x; ah[1] = v.y; ah[2] = v.z; ah[3] = v.w;
                uint4 w2 = *(const uint4*)(smem + SB_AF + 65536 / 2 +
                    ((size_t)((mt * 32 + ks) * 32 + lane)) * 16);
                al[0] = w2.x; al[1] = w2.y; al[2] = w2.z; al[3] = w2.w;
            }
#pragma unroll
            for (int j = 0; j < 4; j++) {
                const int n8t = nh * 4 + j;
                const char* bb = smem + SB_HF +
                    ((size_t)((ks * 2 + 0) * 8 + n8t) * 32 + lane) * 8;
                u64 bh = *(const u64*)bb;
                u64 bl = *(const u64*)(bb + 512 * 4);
                u32 bh0 = (u32)bh, bh1 = (u32)(bh >> 32);
                u32 bl0 = (u32)bl, bl1 = (u32)(bl >> 32);
                mma16816(c[j], ah, bh0, bh1);
                mma16816(c[j], al, bh0, bh1);
                mma16816(c[j], ah, bl0, bl1);
            }
        }

        {
            float* dp = Dex + kh * 2112;
            const int row0 = mt * 16 + lg;
#pragma unroll
            for (int j = 0; j < 4; j++) {
                const int col = (nh * 4 + j) * 8 + 2 * lt;
                *(float2*)&dp[row0 * 66 + col]       = make_float2(c[j][0], c[j][1]);
                *(float2*)&dp[(row0 + 8) * 66 + col] = make_float2(c[j][2], c[j][3]);
            }
        }
        __syncthreads();

        // ---- epilogue: publish h first, then signal, then out store ----
        float hn[2];
        {
#pragma unroll
            for (int q = 0; q < 2; q++) {
                const int u = u0 + q;
                float pi = Dex[u * 66 + b]        + Dex[2112 + u * 66 + b]        + gv[q][0];
                float pf = Dex[(8 + u) * 66 + b]  + Dex[2112 + (8 + u) * 66 + b]  + gv[q][1];
                float pg = Dex[(16 + u) * 66 + b] + Dex[2112 + (16 + u) * 66 + b] + gv[q][2];
                float po = Dex[(24 + u) * 66 + b] + Dex[2112 + (24 + u) * 66 + b] + gv[q][3];
                float ig = sigf(pi), fg = sigf(pf);
                float gg = tanhfast(pg), og = sigf(po);
                float c_old = cs[u * 66 + b];
                float c2 = fg * c_old + ig * gg;
                float h2 = og * tanhfast(c2);
                float c_new = c_old + m * (c2 - c_old);
                float h_old = hs[u * 66 + b];
                float h_new = h_old + m * (h2 - h_old);
                cs[u * 66 + b] = c_new;
                hs[u * 66 + b] = h_new;
                hn[q] = h_new;
            }
            float b0h = __bfloat162float(__float2bfloat16(hn[0]));
            float b1h = __bfloat162float(__float2bfloat16(hn[1]));
            u32 hi = packbf2(hn[0], hn[1]);
            u32 lo = packbf2(hn[0] - b0h, hn[1] - b1h);
            const int ks2 = j0 >> 4;
            const int reg = (j0 & 15) >> 3;
            const int n8t = b >> 3;
            const int lane2 = (b & 7) * 4 + (u0 >> 1);
            u32* dst = &g_hfrag[nb][dir][((ks2 * 2 + 0) * 8 + n8t) * 64 + lane2 * 2 + reg];
            dst[0]   = hi;
            dst[512] = lo;
        }
        // release: CTA-ordering via bar, causal visibility via thread0 fence
        __syncthreads();
        if (tid == 0) {
            __threadfence();
            atomicAdd(&g_rdy[dir][mychunk], 1u);
        }

        // loader for step s+1: one chunk per warp, parallel spins
        if (s + 1 < TT && lane == 0) {
            const unsigned target = 8u * (unsigned)(s + 1);
            while (*(volatile unsigned*)&g_rdy[dir][wid] < target) { }
            mbar_expect_tx(MB + wid * 8, 16384u);
            bulk_g2s(hf_sa + (unsigned)wid * 16384u,
                     &g_hfrag[nb][dir][wid * 4096], 16384u, MB + wid * 8);
        }

        // output store
        *(float2*)&out[(size_t)tg * (BB * 1024) + (size_t)b * 1024
                       + dir * HH + j0 + u0] = make_float2(hn[0], hn[1]);
    }
}

// ---------------- Launch ----------------
extern "C" void kernel_launch(void* const* d_in, const int* in_sizes, int n_in,
                              void* d_out, int out_size) {
    const float* x_data = (const float*)d_in[0];
    const float* x_mask = (const float*)d_in[1];
    const float* Wih_f  = (const float*)d_in[2];
    const float* Whh_f  = (const float*)d_in[3];
    const float* bih_f  = (const float*)d_in[4];
    const float* bhh_f  = (const float*)d_in[5];
    const float* Wih_r  = (const float*)d_in[6];
    const float* Whh_r  = (const float*)d_in[7];
    const float* bih_r  = (const float*)d_in[8];
    const float* bhh_r  = (const float*)d_in[9];
    float* out = (float*)d_out;

    static bool attr_set = false;
    if (!attr_set) {
        cudaFuncSetAttribute(phase2_kernel,
                             cudaFuncAttributeMaxDynamicSharedMemorySize, SMEM2);
        cudaFuncSetAttribute(phase1_mma_kernel,
                             cudaFuncAttributeMaxDynamicSharedMemorySize, P1_SMEM);
        attr_set = true;
    }
    xconv_kernel<<<32768, 256>>>(x_data);
    prep1_kernel<<<256, 256>>>(Wih_f, Wih_r);
    prep_kernel<<<NCTA, 256>>>(Whh_f, Whh_r);
    phase1_mma_kernel<<<dim3(16, 256, 2), 256, P1_SMEM>>>(bih_f, bhh_f, bih_r, bhh_r);
    phase2_kernel<<<NCTA, 256, SMEM2>>>(x_mask, out);
}